// round 9
// baseline (speedup 1.0000x reference)
#include <cuda_runtime.h>
#include <math_constants.h>

// Problem constants (fixed shapes from the reference)
#define BB   8
#define NN   8192
#define SS   2048
#define DD   256
#define QB   128          // queries per block
#define EPSF 1e-8f

// Block: 128 threads. Phase 1: thread t owns query (tile, t), scans all S=2048
// source points from shared, keeps top-3 (smallest squared distance) with
// indices. Phase 2: the 4 warps cooperatively gather D=256 features for each
// of the 128 queries with fully coalesced float4 traffic (points2 is
// L2-resident: 16.8 MB total < 126 MB L2).
__global__ __launch_bounds__(QB)
void fp_interp_kernel(const float* __restrict__ xyz1,     // [B,3,N]
                      const float* __restrict__ xyz2,     // [B,3,S]
                      const float* __restrict__ points2,  // [B,S,D]
                      float* __restrict__ out)            // [B,N,D]
{
    __shared__ float4 sxyz[SS];        // 32 KB: source points (x,y,z,pad)
    __shared__ int    sidx[QB][3];
    __shared__ float  swgt[QB][3];

    const int tile = blockIdx.x;       // 0..511  (64 tiles per batch)
    const int b    = tile >> 6;
    const int n0   = (tile & 63) * QB;
    const int tid  = threadIdx.x;

    // --- stage xyz2[b] into shared (coalesced per component) ---
    const float* x2b = xyz2 + (size_t)b * 3 * SS;
    #pragma unroll
    for (int s = tid; s < SS; s += QB) {
        sxyz[s] = make_float4(x2b[s], x2b[SS + s], x2b[2 * SS + s], 0.0f);
    }
    __syncthreads();

    // --- phase 1: per-thread top-3 scan ---
    const int n = n0 + tid;
    const float* x1b = xyz1 + (size_t)b * 3 * NN;
    const float qx = x1b[n];
    const float qy = x1b[NN + n];
    const float qz = x1b[2 * NN + n];

    float d0 = CUDART_MAX_NORMAL_F, d1 = CUDART_MAX_NORMAL_F, d2 = CUDART_MAX_NORMAL_F;
    int   i0 = 0, i1 = 0, i2 = 0;

    #pragma unroll 8
    for (int s = 0; s < SS; ++s) {
        const float4 p = sxyz[s];                 // broadcast LDS.128
        const float dx = qx - p.x;
        const float dy = qy - p.y;
        const float dz = qz - p.z;
        const float d  = dx * dx + dy * dy + dz * dz;
        if (d < d2) {                             // rare path (~1%/lane)
            if (d < d1) {
                d2 = d1; i2 = i1;
                if (d < d0) { d1 = d0; i1 = i0; d0 = d; i0 = s; }
                else        { d1 = d;  i1 = s; }
            } else { d2 = d; i2 = s; }
        }
    }

    // inverse-distance weights (matches: recip = 1/(d+eps); w = recip/sum)
    const float r0 = 1.0f / (d0 + EPSF);
    const float r1 = 1.0f / (d1 + EPSF);
    const float r2 = 1.0f / (d2 + EPSF);
    const float inv = 1.0f / (r0 + r1 + r2);
    sidx[tid][0] = i0; sidx[tid][1] = i1; sidx[tid][2] = i2;
    swgt[tid][0] = r0 * inv; swgt[tid][1] = r1 * inv; swgt[tid][2] = r2 * inv;
    __syncthreads();

    // --- phase 2: cooperative gather + weighted sum, coalesced float4 ---
    const int warp = tid >> 5;
    const int lane = tid & 31;
    const float4* p2 = (const float4*)(points2 + (size_t)b * SS * DD); // rows of 64 float4
    float4* ob = (float4*)(out + ((size_t)b * NN + n0) * DD);

    for (int q = warp; q < QB; q += QB / 32) {
        const int j0 = sidx[q][0] * (DD / 4);
        const int j1 = sidx[q][1] * (DD / 4);
        const int j2 = sidx[q][2] * (DD / 4);
        const float w0 = swgt[q][0];
        const float w1 = swgt[q][1];
        const float w2 = swgt[q][2];
        float4* oq = ob + (size_t)q * (DD / 4);
        #pragma unroll
        for (int j = lane; j < DD / 4; j += 32) {
            const float4 a = p2[j0 + j];
            const float4 c = p2[j1 + j];
            const float4 e = p2[j2 + j];
            float4 r;
            r.x = w0 * a.x + w1 * c.x + w2 * e.x;
            r.y = w0 * a.y + w1 * c.y + w2 * e.y;
            r.z = w0 * a.z + w1 * c.z + w2 * e.z;
            r.w = w0 * a.w + w1 * c.w + w2 * e.w;
            oq[j] = r;
        }
    }
}

extern "C" void kernel_launch(void* const* d_in, const int* in_sizes, int n_in,
                              void* d_out, int out_size)
{
    // metadata order: xyz1 [B,3,N], xyz2 [B,3,S], points1 [B,D,N] (UNUSED by
    // the reference), points2 [B,S,D]. Output: [B,N,D] float32.
    const float* xyz1    = (const float*)d_in[0];
    const float* xyz2    = (const float*)d_in[1];
    const float* points2 = (const float*)d_in[3];
    float* out = (float*)d_out;

    const int blocks = BB * (NN / QB);   // 8 * 64 = 512
    fp_interp_kernel<<<blocks, QB>>>(xyz1, xyz2, points2, out);
}

// round 10
// speedup vs baseline: 1.2123x; 1.2123x over previous
#include <cuda_runtime.h>
#include <math_constants.h>

// Problem constants (fixed shapes from the reference)
#define BB   8
#define NN   8192
#define SS   2048
#define DD   256
#define QB   128          // queries per block
#define TPB  256          // 2 threads per query (S split in half)
#define SHALF (SS / 2)
#define EPSF 1e-8f

// Insert (t,s) into ascending top-3 (d0<=d1<=d2). Guarded by caller's min-filter.
#define INSERT3(t, s)                                                   \
    if ((t) < d2) {                                                     \
        if ((t) < d1) {                                                 \
            d2 = d1; i2 = i1;                                           \
            if ((t) < d0) { d1 = d0; i1 = i0; d0 = (t); i0 = (s); }     \
            else          { d1 = (t); i1 = (s); }                       \
        } else { d2 = (t); i2 = (s); }                                  \
    }

__global__ __launch_bounds__(TPB)
void fp_interp_kernel(const float* __restrict__ xyz1,     // [B,3,N]
                      const float* __restrict__ xyz2,     // [B,3,S]
                      const float* __restrict__ points2,  // [B,S,D]
                      float* __restrict__ out)            // [B,N,D]
{
    __shared__ float4 sxyz[SS];        // 32 KB: (x, y, z, |p|^2)
    __shared__ float  smd[QB][3];      // partner-half top3 t-values
    __shared__ int    smi[QB][3];      // partner-half top3 indices
    __shared__ float  swgt[QB][3];
    __shared__ int    sidx[QB][3];

    const int tile = blockIdx.x;       // 0..511
    const int b    = tile >> 6;
    const int n0   = (tile & 63) * QB;
    const int tid  = threadIdx.x;

    // --- stage xyz2[b] into shared with precomputed |p|^2 ---
    const float* x2b = xyz2 + (size_t)b * 3 * SS;
    #pragma unroll
    for (int s = tid; s < SS; s += TPB) {
        const float x = x2b[s], y = x2b[SS + s], z = x2b[2 * SS + s];
        sxyz[s] = make_float4(x, y, z, fmaf(x, x, fmaf(y, y, z * z)));
    }
    __syncthreads();

    // --- phase 1: split-S top-3 scan. t = |p|^2 - 2 q.p  (order == order of d) ---
    const int q    = tid & (QB - 1);
    const int half = tid >> 7;         // 0 or 1
    const int n    = n0 + q;
    const float* x1b = xyz1 + (size_t)b * 3 * NN;
    const float qx = x1b[n], qy = x1b[NN + n], qz = x1b[2 * NN + n];
    const float ax = -2.0f * qx, ay = -2.0f * qy, az = -2.0f * qz;
    const float qq = fmaf(qx, qx, fmaf(qy, qy, qz * qz));

    float d0 = CUDART_MAX_NORMAL_F, d1 = CUDART_MAX_NORMAL_F, d2 = CUDART_MAX_NORMAL_F;
    int   i0 = 0, i1 = 0, i2 = 0;

    const int sbeg = half * SHALF;
    #pragma unroll 2
    for (int s = sbeg; s < sbeg + SHALF; s += 4) {
        const float4 p0 = sxyz[s];
        const float4 p1 = sxyz[s + 1];
        const float4 p2 = sxyz[s + 2];
        const float4 p3 = sxyz[s + 3];
        const float t0 = fmaf(p0.x, ax, fmaf(p0.y, ay, fmaf(p0.z, az, p0.w)));
        const float t1 = fmaf(p1.x, ax, fmaf(p1.y, ay, fmaf(p1.z, az, p1.w)));
        const float t2 = fmaf(p2.x, ax, fmaf(p2.y, ay, fmaf(p2.z, az, p2.w)));
        const float t3 = fmaf(p3.x, ax, fmaf(p3.y, ay, fmaf(p3.z, az, p3.w)));
        const float m  = fminf(fminf(t0, t1), fminf(t2, t3));
        if (m < d2) {                      // rare (~5%/lane per group)
            INSERT3(t0, s)
            INSERT3(t1, s + 1)
            INSERT3(t2, s + 2)
            INSERT3(t3, s + 3)
        }
    }

    // --- merge halves: upper half publishes, lower half merges + weights ---
    if (half) {
        smd[q][0] = d0; smd[q][1] = d1; smd[q][2] = d2;
        smi[q][0] = i0; smi[q][1] = i1; smi[q][2] = i2;
    }
    __syncthreads();
    if (!half) {
        const float bd0 = smd[q][0], bd1 = smd[q][1], bd2 = smd[q][2];
        const int   bi0 = smi[q][0], bi1 = smi[q][1], bi2 = smi[q][2];
        float rd0, rd1, rd2; int ri0, ri1, ri2;
        if (d0 <= bd0) {
            rd0 = d0; ri0 = i0;
            if (d1 <= bd0) {
                rd1 = d1; ri1 = i1;
                if (d2 <= bd0) { rd2 = d2;  ri2 = i2;  }
                else           { rd2 = bd0; ri2 = bi0; }
            } else {
                rd1 = bd0; ri1 = bi0;
                if (d1 <= bd1) { rd2 = d1;  ri2 = i1;  }
                else           { rd2 = bd1; ri2 = bi1; }
            }
        } else {
            rd0 = bd0; ri0 = bi0;
            if (bd1 <= d0) {
                rd1 = bd1; ri1 = bi1;
                if (bd2 <= d0) { rd2 = bd2; ri2 = bi2; }
                else           { rd2 = d0;  ri2 = i0;  }
            } else {
                rd1 = d0; ri1 = i0;
                if (d1 <= bd1) { rd2 = d1;  ri2 = i1;  }
                else           { rd2 = bd1; ri2 = bi1; }
            }
        }
        // true squared distances and inverse-distance weights
        const float r0 = 1.0f / ((rd0 + qq) + EPSF);
        const float r1 = 1.0f / ((rd1 + qq) + EPSF);
        const float r2 = 1.0f / ((rd2 + qq) + EPSF);
        const float inv = 1.0f / (r0 + r1 + r2);
        sidx[q][0] = ri0; sidx[q][1] = ri1; sidx[q][2] = ri2;
        swgt[q][0] = r0 * inv; swgt[q][1] = r1 * inv; swgt[q][2] = r2 * inv;
    }
    __syncthreads();

    // --- phase 2: cooperative gather + weighted sum, coalesced float4 ---
    const int warp = tid >> 5;
    const int lane = tid & 31;
    const float4* p2f = (const float4*)(points2 + (size_t)b * SS * DD); // rows of 64 float4
    float4* ob = (float4*)(out + ((size_t)b * NN + n0) * DD);

    for (int qi = warp; qi < QB; qi += TPB / 32) {
        const int j0 = sidx[qi][0] * (DD / 4);
        const int j1 = sidx[qi][1] * (DD / 4);
        const int j2 = sidx[qi][2] * (DD / 4);
        const float w0 = swgt[qi][0];
        const float w1 = swgt[qi][1];
        const float w2 = swgt[qi][2];
        float4* oq = ob + (size_t)qi * (DD / 4);
        #pragma unroll
        for (int j = lane; j < DD / 4; j += 32) {
            const float4 a = p2f[j0 + j];
            const float4 c = p2f[j1 + j];
            const float4 e = p2f[j2 + j];
            float4 r;
            r.x = w0 * a.x + w1 * c.x + w2 * e.x;
            r.y = w0 * a.y + w1 * c.y + w2 * e.y;
            r.z = w0 * a.z + w1 * c.z + w2 * e.z;
            r.w = w0 * a.w + w1 * c.w + w2 * e.w;
            oq[j] = r;
        }
    }
}

extern "C" void kernel_launch(void* const* d_in, const int* in_sizes, int n_in,
                              void* d_out, int out_size)
{
    // inputs: xyz1 [B,3,N], xyz2 [B,3,S], points1 [B,D,N] (unused), points2 [B,S,D]
    const float* xyz1    = (const float*)d_in[0];
    const float* xyz2    = (const float*)d_in[1];
    const float* points2 = (const float*)d_in[3];
    float* out = (float*)d_out;

    const int blocks = BB * (NN / QB);   // 512
    fp_interp_kernel<<<blocks, TPB>>>(xyz1, xyz2, points2, out);
}